// round 5
// baseline (speedup 1.0000x reference)
#include <cuda_runtime.h>
#include <cuda_bf16.h>
#include <stdint.h>

#define HEADS 16
#define MDIM 4096
#define NDIM 4096
#define KDIM 64
#define QBLK 32

// Int8 BFP mantissas (rhs stored transposed: [h][n][k]) + per-(row, kblock)
// fp32 steps (powers of two), layout [h][kb][row].
static __device__ int8_t g_lhs_q[(size_t)HEADS * MDIM * KDIM];
static __device__ int8_t g_rhs_q[(size_t)HEADS * NDIM * KDIM];
static __device__ float  g_lhs_s[(size_t)HEADS * 2 * MDIM];
static __device__ float  g_rhs_s[(size_t)HEADS * 2 * NDIM];

// ===========================================================================
// Quant: two adjacent threads share one 32-block (block max via shfl_xor).
// Emits int8 mantissas q = clip(rint(x * 2^(7-e)), -128, 127) and the step
// 2^(e-7). q*step reproduces the reference dequant exactly.
// ===========================================================================
__device__ __forceinline__ void quant_half16_q(float v[16], float& step_out) {
    float ma = 0.f;
#pragma unroll
    for (int i = 0; i < 16; i++) ma = fmaxf(ma, fabsf(v[i]));
    ma = fmaxf(ma, __shfl_xor_sync(0xFFFFFFFFu, ma, 1));  // full 32-block max
    if (ma > 0.f) {
        int e = ilogbf(fmaxf(ma, 1e-38f));       // floor(log2(.)) exactly
        float scale = exp2f((float)(7 - e));     // exact power of two
        step_out    = exp2f((float)(e - 7));
#pragma unroll
        for (int i = 0; i < 16; i++) {
            float q = rintf(v[i] * scale);       // round-half-even
            v[i] = fminf(fmaxf(q, -128.f), 127.f);
        }
    } else {
        step_out = 0.f;
#pragma unroll
        for (int i = 0; i < 16; i++) v[i] = 0.f;
    }
}

__device__ __forceinline__ void pack_q16(int8_t* dst, const float v[16]) {
    uint32_t pk[4];
#pragma unroll
    for (int j = 0; j < 4; j++) {
        uint32_t b0 = (uint32_t)(uint8_t)(int8_t)(int)v[4 * j + 0];
        uint32_t b1 = (uint32_t)(uint8_t)(int8_t)(int)v[4 * j + 1];
        uint32_t b2 = (uint32_t)(uint8_t)(int8_t)(int)v[4 * j + 2];
        uint32_t b3 = (uint32_t)(uint8_t)(int8_t)(int)v[4 * j + 3];
        pk[j] = b0 | (b1 << 8) | (b2 << 16) | (b3 << 24);
    }
    *reinterpret_cast<uint4*>(dst) = make_uint4(pk[0], pk[1], pk[2], pk[3]);
}

#define QL_BLOCKS 1024
#define QR_BLOCKS 1024

__global__ void __launch_bounds__(256) quant_all_kernel(
    const float* __restrict__ lhs, const float* __restrict__ rhs) {
    if (blockIdx.x < QL_BLOCKS) {
        // lhs [h][m][64]: thread owns 16 consecutive floats.
        size_t t = blockIdx.x * (size_t)blockDim.x + threadIdx.x;
        const float4* src = reinterpret_cast<const float4*>(lhs + t * 16);
        float v[16];
#pragma unroll
        for (int j = 0; j < 4; j++) {
            float4 f = __ldg(src + j);
            v[4 * j] = f.x; v[4 * j + 1] = f.y; v[4 * j + 2] = f.z; v[4 * j + 3] = f.w;
        }
        float step;
        quant_half16_q(v, step);
        pack_q16(g_lhs_q + t * 16, v);
        if ((t & 1) == 0) {
            size_t b = t >> 1;                       // 32-block index
            int kb = (int)(b & 1);
            int m  = (int)((b >> 1) & (MDIM - 1));
            int h  = (int)(b >> 13);
            g_lhs_s[((size_t)h * 2 + kb) * MDIM + m] = step;
        }
    } else {
        // rhs [h][k=64][n]: blocks along k (stride NDIM); transpose on write.
        int t    = (blockIdx.x - QL_BLOCKS) * blockDim.x + threadIdx.x;
        int half = t & 1;
        int pair = t >> 1;
        int c  = pair & (NDIM - 1);
        int kb = (pair >> 12) & 1;
        int h  = pair >> 13;
        const float* src = rhs + ((size_t)h * KDIM + kb * QBLK + half * 16) * NDIM + c;
        float v[16];
#pragma unroll
        for (int k = 0; k < 16; k++) v[k] = __ldg(src + (size_t)k * NDIM);
        float step;
        quant_half16_q(v, step);
        pack_q16(g_rhs_q + (((size_t)h * NDIM + c) * KDIM + kb * QBLK + half * 16), v);
        if (half == 0)
            g_rhs_s[((size_t)h * 2 + kb) * NDIM + c] = step;
    }
}

// ===========================================================================
// GEMM: out[h][m][n] = sum_kb  s32mma(qA, qB) * sa[m,kb] * sb[n,kb]
// 128x128 tile, 8 warps = 4(m) x 2(n), each warp 32x64 via m16n8k32 s8 mma.
// One mma per (mt, nt, kb) with C=0; scales folded immediately into fp32 acc.
// ===========================================================================
#define PITCH 80   // bytes per smem row (64 data + pad): conflict-free ldmatrix

__global__ void __launch_bounds__(256) bfp_gemm_kernel(float* __restrict__ out) {
    __shared__ int8_t sA[128 * PITCH];
    __shared__ int8_t sB[128 * PITCH];
    __shared__ float  sAs[2][128];
    __shared__ float  sBs[2][128];

    const int h  = blockIdx.z;
    const int bm = blockIdx.y, bn = blockIdx.x;
    const int8_t* gA = g_lhs_q + ((size_t)h * MDIM + bm * 128) * KDIM;
    const int8_t* gB = g_rhs_q + ((size_t)h * NDIM + bn * 128) * KDIM;
    const int tid = threadIdx.x;

    // operand tiles: 128 rows x 64B = 512 uint4 each; 256 threads x 2 per tile
#pragma unroll
    for (int i = 0; i < 2; i++) {
        int idx = i * 256 + tid;
        int r = idx >> 2, j = idx & 3;
        *reinterpret_cast<uint4*>(&sA[r * PITCH + j * 16]) =
            *reinterpret_cast<const uint4*>(gA + r * KDIM + j * 16);
        *reinterpret_cast<uint4*>(&sB[r * PITCH + j * 16]) =
            *reinterpret_cast<const uint4*>(gB + r * KDIM + j * 16);
    }
    // scales: 256 floats each
    {
        int kb = tid >> 7, i = tid & 127;
        sAs[kb][i] = g_lhs_s[((size_t)h * 2 + kb) * MDIM + bm * 128 + i];
        sBs[kb][i] = g_rhs_s[((size_t)h * 2 + kb) * NDIM + bn * 128 + i];
    }
    __syncthreads();

    const int lane = tid & 31;
    const int wid  = tid >> 5;
    const int wm   = (wid >> 1) * 32;   // warp row base
    const int wn   = (wid & 1) * 64;    // warp col base

    float acc[2][8][4];
#pragma unroll
    for (int mt = 0; mt < 2; mt++)
#pragma unroll
        for (int nt = 0; nt < 8; nt++)
#pragma unroll
            for (int i = 0; i < 4; i++) acc[mt][nt][i] = 0.f;

    const int zero = 0;

#pragma unroll
    for (int kb = 0; kb < 2; kb++) {
        // A fragments: m16 x k32 int8 via ldmatrix b16 x4
        uint32_t a[2][4];
#pragma unroll
        for (int mt = 0; mt < 2; mt++) {
            int row = wm + mt * 16 + (lane & 15);
            int col = kb * 32 + (lane >> 4) * 16;
            uint32_t addr = (uint32_t)__cvta_generic_to_shared(&sA[row * PITCH + col]);
            asm volatile("ldmatrix.sync.aligned.m8n8.x4.shared.b16 {%0,%1,%2,%3}, [%4];\n"
                         : "=r"(a[mt][0]), "=r"(a[mt][1]), "=r"(a[mt][2]), "=r"(a[mt][3])
                         : "r"(addr));
        }
        // per-mt row scales (rows lane>>2 and +8)
        float saL[2], saH[2];
#pragma unroll
        for (int mt = 0; mt < 2; mt++) {
            saL[mt] = sAs[kb][wm + mt * 16 + (lane >> 2)];
            saH[mt] = sAs[kb][wm + mt * 16 + (lane >> 2) + 8];
        }
#pragma unroll
        for (int nt = 0; nt < 8; nt++) {
            int row = wn + nt * 8 + (lane & 7);
            int col = kb * 32 + ((lane >> 3) & 1) * 16;
            uint32_t addr = (uint32_t)__cvta_generic_to_shared(&sB[row * PITCH + col]);
            uint32_t b0, b1;
            asm volatile("ldmatrix.sync.aligned.m8n8.x2.shared.b16 {%0,%1}, [%2];\n"
                         : "=r"(b0), "=r"(b1) : "r"(addr));
            float sb0 = sBs[kb][wn + nt * 8 + (lane & 3) * 2];
            float sb1 = sBs[kb][wn + nt * 8 + (lane & 3) * 2 + 1];
#pragma unroll
            for (int mt = 0; mt < 2; mt++) {
                int d0, d1, d2, d3;
                asm volatile(
                    "mma.sync.aligned.m16n8k32.row.col.s32.s8.s8.s32 "
                    "{%0,%1,%2,%3}, {%4,%5,%6,%7}, {%8,%9}, {%10,%10,%10,%10};\n"
                    : "=r"(d0), "=r"(d1), "=r"(d2), "=r"(d3)
                    : "r"(a[mt][0]), "r"(a[mt][1]), "r"(a[mt][2]), "r"(a[mt][3]),
                      "r"(b0), "r"(b1), "r"(zero));
                // exact: |d| <= 2^19, scales are powers of two
                acc[mt][nt][0] += __int2float_rn(d0) * (saL[mt] * sb0);
                acc[mt][nt][1] += __int2float_rn(d1) * (saL[mt] * sb1);
                acc[mt][nt][2] += __int2float_rn(d2) * (saH[mt] * sb0);
                acc[mt][nt][3] += __int2float_rn(d3) * (saH[mt] * sb1);
            }
        }
    }

    // Streaming stores: 32B-sector-aligned float2 per lane, evict-first.
    float* gO = out + (size_t)h * MDIM * NDIM + (size_t)(bm * 128) * NDIM + bn * 128;
#pragma unroll
    for (int mt = 0; mt < 2; mt++) {
#pragma unroll
        for (int nt = 0; nt < 8; nt++) {
            int r0 = wm + mt * 16 + (lane >> 2);
            int c0 = wn + nt * 8 + (lane & 3) * 2;
            __stcs(reinterpret_cast<float2*>(&gO[(size_t)r0 * NDIM + c0]),
                   make_float2(acc[mt][nt][0], acc[mt][nt][1]));
            __stcs(reinterpret_cast<float2*>(&gO[(size_t)(r0 + 8) * NDIM + c0]),
                   make_float2(acc[mt][nt][2], acc[mt][nt][3]));
        }
    }
}

extern "C" void kernel_launch(void* const* d_in, const int* in_sizes, int n_in,
                              void* d_out, int out_size) {
    (void)in_sizes; (void)n_in; (void)out_size;
    const float* lhs = (const float*)d_in[0];  // [1,16,4096,64]
    const float* rhs = (const float*)d_in[1];  // [1,16,64,4096]
    float* out = (float*)d_out;                // [1,16,4096,4096]

    quant_all_kernel<<<QL_BLOCKS + QR_BLOCKS, 256>>>(lhs, rhs);

    dim3 grid(NDIM / 128, MDIM / 128, HEADS);
    bfp_gemm_kernel<<<grid, 256>>>(out);
}